// round 2
// baseline (speedup 1.0000x reference)
#include <cuda_runtime.h>
#include <math.h>

// ---- problem shape ----
#define BATCH 4
#define SEQL  1024
#define DM    1024
#define NH    16
#define HD    64
#define FF    4096
#define NE    8
#define TOPK  2
#define NTOK  (BATCH*SEQL)          // 4096 tokens
#define NSLOT 8704                  // 4096*2 + worst-case 64-align padding (8*63=504) -> 8696 <= 8704

// GEMM tiling
#define BM 64
#define BN 64
#define BK 16

// ---- scratch (device globals; no runtime allocation allowed) ----
__device__ float g_nx  [(size_t)NTOK*DM];
__device__ float g_qkv [(size_t)NTOK*3*DM];
__device__ float g_attn[(size_t)NTOK*DM];
__device__ float g_x1  [(size_t)NTOK*DM];
__device__ float g_nx2 [(size_t)NTOK*DM];
__device__ int   g_top_idx[NTOK*TOPK];
__device__ float g_top_w  [NTOK*TOPK];
__device__ int   g_cnt [NE];
__device__ int   g_off [NE+1];
__device__ int   g_fill[NE];
__device__ int   g_slot2tok[NSLOT];
__device__ int   g_slot_expert[NSLOT];
__device__ int   g_tok2slot[NTOK*TOPK];
__device__ float g_h[(size_t)NSLOT*FF];
__device__ float g_y[(size_t)NSLOT*DM];

// ---------------- LayerNorm (x -> out), both via pointers ----------------
__device__ __forceinline__ void ln_body(const float* __restrict__ x, const float* __restrict__ w,
                                        const float* __restrict__ b, float* __restrict__ out) {
    int t = blockIdx.x;
    const float* row = x + (size_t)t * DM;
    float s = 0.f, s2 = 0.f;
    for (int i = threadIdx.x; i < DM; i += blockDim.x) {
        float v = row[i]; s += v; s2 += v * v;
    }
    __shared__ float sh[64];
    for (int o = 16; o > 0; o >>= 1) {
        s  += __shfl_down_sync(0xffffffffu, s,  o);
        s2 += __shfl_down_sync(0xffffffffu, s2, o);
    }
    int wid = threadIdx.x >> 5, lane = threadIdx.x & 31;
    if (lane == 0) { sh[wid] = s; sh[wid + 32] = s2; }
    __syncthreads();
    if (threadIdx.x == 0) {
        float a = 0.f, c = 0.f;
        int nw = blockDim.x >> 5;
        for (int i = 0; i < nw; i++) { a += sh[i]; c += sh[i + 32]; }
        float mu  = a / DM;
        float var = c / DM - mu * mu;
        sh[0] = mu; sh[1] = rsqrtf(var + 1e-5f);
    }
    __syncthreads();
    float mu = sh[0], rs = sh[1];
    for (int i = threadIdx.x; i < DM; i += blockDim.x)
        out[(size_t)t * DM + i] = (row[i] - mu) * rs * w[i] + b[i];
}

__global__ void __launch_bounds__(256) ln1_kernel(const float* __restrict__ x,
                                                  const float* __restrict__ w,
                                                  const float* __restrict__ b) {
    ln_body(x, w, b, g_nx);
}
__global__ void __launch_bounds__(256) ln2_kernel(const float* __restrict__ w,
                                                  const float* __restrict__ b) {
    ln_body(g_x1, w, b, g_nx2);
}

// ---------------- GEMM body (C = A[M,K] @ B[K,N] + bias (+resid), opt GELU) ----------------
__device__ __forceinline__ void gemm_nn_body(const float* __restrict__ A, const float* __restrict__ Bm,
                                             const float* __restrict__ bias, const float* __restrict__ resid,
                                             float* __restrict__ C, int N, int K, int act) {
    __shared__ float As[BK][BM];
    __shared__ float Bs[BK][BN + 1];
    int m0 = blockIdx.y * BM, n0 = blockIdx.x * BN;
    int tid = threadIdx.x;
    int tx = tid & 15, ty = tid >> 4;
    float acc[4][4] = {};
    for (int k0 = 0; k0 < K; k0 += BK) {
        for (int i = tid; i < BM * BK; i += 256) {
            int m = i >> 4, k = i & 15;
            As[k][m] = A[(size_t)(m0 + m) * K + k0 + k];
        }
        for (int i = tid; i < BK * BN; i += 256) {
            int k = i >> 6, n = i & 63;
            Bs[k][n] = Bm[(size_t)(k0 + k) * N + n0 + n];
        }
        __syncthreads();
#pragma unroll
        for (int k = 0; k < BK; k++) {
            float a[4], bb[4];
#pragma unroll
            for (int i = 0; i < 4; i++) { a[i] = As[k][ty * 4 + i]; bb[i] = Bs[k][tx * 4 + i]; }
#pragma unroll
            for (int i = 0; i < 4; i++)
#pragma unroll
                for (int j = 0; j < 4; j++) acc[i][j] += a[i] * bb[j];
        }
        __syncthreads();
    }
    for (int i = 0; i < 4; i++) {
        int m = m0 + ty * 4 + i;
        for (int j = 0; j < 4; j++) {
            int n = n0 + tx * 4 + j;
            float v = acc[i][j];
            if (bias)  v += bias[n];
            if (act == 1) v = 0.5f * v * (1.0f + erff(v * 0.70710678118654752f));
            if (resid) v += resid[(size_t)m * N + n];
            C[(size_t)m * N + n] = v;
        }
    }
}

// wrappers binding the scratch globals (no host symbol lookup needed)
__global__ void __launch_bounds__(256) gemm_qkv(const float* __restrict__ Wqkv,
                                                const float* __restrict__ bqkv) {
    gemm_nn_body(g_nx, Wqkv, bqkv, nullptr, g_qkv, 3 * DM, DM, 0);
}
__global__ void __launch_bounds__(256) gemm_wo(const float* __restrict__ Wo,
                                               const float* __restrict__ bo,
                                               const float* __restrict__ x) {
    gemm_nn_body(g_attn, Wo, bo, x, g_x1, DM, DM, 0);
}

// ------- grouped MoE GEMM: C[slot,N] = gather(A)[slot,K] @ W[e]^T + bias[e] (opt GELU) -------
__device__ __forceinline__ void moe_gemm_nt_body(const float* __restrict__ A, int lda, int use_rowmap,
                                                 const float* __restrict__ Wbase, size_t wstride,
                                                 const float* __restrict__ biasbase, int bstride,
                                                 float* __restrict__ C, int N, int K, int act) {
    int m0 = blockIdx.y * BM;
    if (m0 >= g_off[NE]) return;             // beyond last used slot
    int e = g_slot_expert[m0];               // tile entirely within one expert (64-aligned offsets)
    const float* Bw   = Wbase   + (size_t)e * wstride;
    const float* bias = biasbase + (size_t)e * bstride;
    __shared__ float As[BK][BM];
    __shared__ float Bs[BK][BN + 1];
    int n0 = blockIdx.x * BN;
    int tid = threadIdx.x;
    int tx = tid & 15, ty = tid >> 4;
    float acc[4][4] = {};
    for (int k0 = 0; k0 < K; k0 += BK) {
        for (int i = tid; i < BM * BK; i += 256) {
            int m = i >> 4, k = i & 15;
            int row = m0 + m;
            int ar = use_rowmap ? g_slot2tok[row] : row;
            As[k][m] = (ar >= 0) ? A[(size_t)ar * lda + k0 + k] : 0.0f;
        }
        for (int i = tid; i < BN * BK; i += 256) {
            int n = i >> 4, k = i & 15;
            Bs[k][n] = Bw[(size_t)(n0 + n) * K + k0 + k];
        }
        __syncthreads();
#pragma unroll
        for (int k = 0; k < BK; k++) {
            float a[4], bb[4];
#pragma unroll
            for (int i = 0; i < 4; i++) { a[i] = As[k][ty * 4 + i]; bb[i] = Bs[k][tx * 4 + i]; }
#pragma unroll
            for (int i = 0; i < 4; i++)
#pragma unroll
                for (int j = 0; j < 4; j++) acc[i][j] += a[i] * bb[j];
        }
        __syncthreads();
    }
    for (int i = 0; i < 4; i++) {
        int m = m0 + ty * 4 + i;
        for (int j = 0; j < 4; j++) {
            int n = n0 + tx * 4 + j;
            float v = acc[i][j] + bias[n];
            if (act == 1) v = 0.5f * v * (1.0f + erff(v * 0.70710678118654752f));
            C[(size_t)m * N + n] = v;
        }
    }
}

__global__ void __launch_bounds__(256) moe_fc1(const float* __restrict__ fc1_w,
                                               const float* __restrict__ fc1_b) {
    moe_gemm_nt_body(g_nx2, DM, 1, fc1_w, (size_t)FF * DM, fc1_b, FF, g_h, FF, DM, 1);
}
__global__ void __launch_bounds__(256) moe_fc2(const float* __restrict__ fc2_w,
                                               const float* __restrict__ fc2_b) {
    moe_gemm_nt_body(g_h, FF, 0, fc2_w, (size_t)DM * FF, fc2_b, DM, g_y, DM, FF, 0);
}

// ---------------- causal attention (one block per (b,h,q) row, online softmax) ----------------
__global__ void __launch_bounds__(128) attn_kernel() {
    const float* __restrict__ qkv = g_qkv;
    int q = blockIdx.x, h = blockIdx.y, b = blockIdx.z;
    int tid = threadIdx.x;  // 128 threads
    __shared__ float qs[HD];
    __shared__ float ps[128];
    __shared__ float red[128];
    __shared__ float acc[HD];
    size_t rowq = ((size_t)(b * SEQL + q) * 3 * DM) + h * HD;
    if (tid < HD) { qs[tid] = qkv[rowq + tid]; acc[tid] = 0.f; }
    float m = -1e30f, l = 0.f;
    __syncthreads();
    for (int k0 = 0; k0 <= q; k0 += 128) {
        int kk = k0 + tid;
        float s = -1e30f;
        if (kk <= q) {
            const float* kp = qkv + ((size_t)(b * SEQL + kk) * 3 * DM) + DM + h * HD;
            float d = 0.f;
#pragma unroll
            for (int i = 0; i < HD; i++) d += qs[i] * kp[i];
            s = d * 0.125f;   // 1/sqrt(64)
        }
        red[tid] = s; __syncthreads();
        for (int o = 64; o > 0; o >>= 1) { if (tid < o) red[tid] = fmaxf(red[tid], red[tid + o]); __syncthreads(); }
        float cm = red[0];
        __syncthreads();
        float nm = fmaxf(m, cm);
        float p = (kk <= q) ? __expf(s - nm) : 0.f;
        ps[tid] = p;
        red[tid] = p; __syncthreads();
        for (int o = 64; o > 0; o >>= 1) { if (tid < o) red[tid] += red[tid + o]; __syncthreads(); }
        float csum = red[0];
        float scale = __expf(m - nm);
        if (tid < HD) {
            float a = acc[tid] * scale;
            int lim = min(128, q - k0 + 1);
            const float* vbase = qkv + ((size_t)(b * SEQL + k0) * 3 * DM) + 2 * DM + h * HD + tid;
            for (int i = 0; i < lim; i++) a += ps[i] * vbase[(size_t)i * 3 * DM];
            acc[tid] = a;
        }
        l = l * scale + csum;
        m = nm;
        __syncthreads();
    }
    if (tid < HD) g_attn[(size_t)(b * SEQL + q) * DM + h * HD + tid] = acc[tid] / l;
}

// ---------------- gating: top-2 + softmax over selected logits ----------------
__global__ void __launch_bounds__(256) gate_kernel(const float* __restrict__ gW) {
    int t = blockIdx.x, tid = threadIdx.x;        // 256 threads = 8 warps = 8 experts
    int e = tid >> 5, lane = tid & 31;
    float s = 0.f;
    for (int d = lane; d < DM; d += 32) s += g_nx2[(size_t)t * DM + d] * gW[(size_t)d * NE + e];
    for (int o = 16; o > 0; o >>= 1) s += __shfl_down_sync(0xffffffffu, s, o);
    __shared__ float lg[NE];
    if (lane == 0) lg[e] = s;
    __syncthreads();
    if (tid == 0) {
        int i0 = 0; float v0 = lg[0];
        for (int i = 1; i < NE; i++) if (lg[i] > v0) { v0 = lg[i]; i0 = i; }
        int i1 = -1; float v1 = -1e30f;
        for (int i = 0; i < NE; i++) { if (i == i0) continue; if (lg[i] > v1) { v1 = lg[i]; i1 = i; } }
        float e1 = expf(v1 - v0), sum = 1.f + e1;
        g_top_idx[t * 2] = i0; g_top_idx[t * 2 + 1] = i1;
        g_top_w[t * 2] = 1.f / sum; g_top_w[t * 2 + 1] = e1 / sum;
    }
}

// ---------------- routing ----------------
__global__ void route_zero() {
    int i = blockIdx.x * blockDim.x + threadIdx.x;
    if (i < NE) { g_cnt[i] = 0; g_fill[i] = 0; }
    if (i < NSLOT) g_slot2tok[i] = -1;
}
__global__ void route_count() {
    int i = blockIdx.x * blockDim.x + threadIdx.x;
    if (i < NTOK * TOPK) atomicAdd(&g_cnt[g_top_idx[i]], 1);
}
__global__ void route_scan() {
    g_off[0] = 0;
    for (int e = 0; e < NE; e++)
        g_off[e + 1] = g_off[e] + ((g_cnt[e] + BM - 1) / BM) * BM;   // 64-aligned per expert
}
__global__ void route_fill_expert() {
    int s = blockIdx.x * blockDim.x + threadIdx.x;
    if (s >= NSLOT) return;
    int e = NE - 1;
    for (int i = 0; i < NE; i++) if (s >= g_off[i] && s < g_off[i + 1]) { e = i; break; }
    g_slot_expert[s] = e;
}
__global__ void route_assign() {
    int i = blockIdx.x * blockDim.x + threadIdx.x;
    if (i >= NTOK * TOPK) return;
    int e = g_top_idx[i];
    int pos = atomicAdd(&g_fill[e], 1);
    int slot = g_off[e] + pos;
    g_slot2tok[slot] = i >> 1;
    g_tok2slot[i] = slot;
}

// ---------------- final combine: out = x1 + sum_k w_k * y[slot_k] ----------------
__global__ void __launch_bounds__(256) combine_kernel(float* __restrict__ out) {
    int t = blockIdx.x;
    int s0 = g_tok2slot[t * 2], s1 = g_tok2slot[t * 2 + 1];
    float w0 = g_top_w[t * 2], w1 = g_top_w[t * 2 + 1];
    for (int i = threadIdx.x; i < DM; i += blockDim.x)
        out[(size_t)t * DM + i] =
            g_x1[(size_t)t * DM + i] + w0 * g_y[(size_t)s0 * DM + i] + w1 * g_y[(size_t)s1 * DM + i];
}

// ---------------- launch: kernel launches ONLY ----------------
extern "C" void kernel_launch(void* const* d_in, const int* in_sizes, int n_in,
                              void* d_out, int out_size) {
    const float* x     = (const float*)d_in[0];
    const float* ln1_w = (const float*)d_in[1];
    const float* ln1_b = (const float*)d_in[2];
    const float* ln2_w = (const float*)d_in[3];
    const float* ln2_b = (const float*)d_in[4];
    const float* Wqkv  = (const float*)d_in[5];
    const float* bqkv  = (const float*)d_in[6];
    const float* Wo    = (const float*)d_in[7];
    const float* bo    = (const float*)d_in[8];
    const float* gateW = (const float*)d_in[9];
    const float* fc1_w = (const float*)d_in[10];
    const float* fc1_b = (const float*)d_in[11];
    const float* fc2_w = (const float*)d_in[12];
    const float* fc2_b = (const float*)d_in[13];
    float* out = (float*)d_out;

    // 1) LN1: g_nx = LN(x)
    ln1_kernel<<<NTOK, 256>>>(x, ln1_w, ln1_b);
    // 2) QKV projection: g_qkv = g_nx @ Wqkv + bqkv
    gemm_qkv<<<dim3(3 * DM / BN, NTOK / BM), 256>>>(Wqkv, bqkv);
    // 3) causal attention: g_attn
    attn_kernel<<<dim3(SEQL, NH, BATCH), 128>>>();
    // 4) output projection + residual: g_x1 = x + g_attn @ Wo + bo
    gemm_wo<<<dim3(DM / BN, NTOK / BM), 256>>>(Wo, bo, x);
    // 5) LN2: g_nx2 = LN(g_x1)
    ln2_kernel<<<NTOK, 256>>>(ln2_w, ln2_b);
    // 6) gate top-2
    gate_kernel<<<NTOK, 256>>>(gateW);
    // 7) routing
    route_zero<<<(NSLOT + 255) / 256, 256>>>();
    route_count<<<(NTOK * TOPK + 255) / 256, 256>>>();
    route_scan<<<1, 1>>>();
    route_fill_expert<<<(NSLOT + 255) / 256, 256>>>();
    route_assign<<<(NTOK * TOPK + 255) / 256, 256>>>();
    // 8) fc1: g_h = gelu(gather(g_nx2) @ fc1_w[e]^T + fc1_b[e])
    moe_fc1<<<dim3(FF / BN, NSLOT / BM), 256>>>(fc1_w, fc1_b);
    // 9) fc2: g_y = g_h @ fc2_w[e]^T + fc2_b[e]
    moe_fc2<<<dim3(DM / BN, NSLOT / BM), 256>>>(fc2_w, fc2_b);
    // 10) combine: out = g_x1 + w0*y0 + w1*y1
    combine_kernel<<<NTOK, 256>>>(out);
    (void)in_sizes; (void)n_in; (void)out_size;
}

// round 4
// speedup vs baseline: 4.0811x; 4.0811x over previous
#include <cuda_runtime.h>
#include <math.h>
#include <stdint.h>

// ---- problem shape ----
#define BATCH 4
#define SEQL  1024
#define DM    1024
#define NH    16
#define HD    64
#define FF    4096
#define NE    8
#define TOPK  2
#define NTOK  (BATCH*SEQL)          // 4096 tokens
#define NSLOT 9216                  // 4096*2 + worst-case 128-align padding (8*127=1016) -> 9208 <= 9216 = 72*128

// GEMM tiling (tensor-core kernel)
#define BM 128
#define BN 64
#define BK 16

// ---- scratch (device globals; no runtime allocation allowed) ----
__device__ float g_nx  [(size_t)NTOK*DM];
__device__ float g_qkv [(size_t)NTOK*3*DM];
__device__ float g_attn[(size_t)NTOK*DM];
__device__ float g_x1  [(size_t)NTOK*DM];
__device__ float g_nx2 [(size_t)NTOK*DM];
__device__ int   g_top_idx[NTOK*TOPK];
__device__ float g_top_w  [NTOK*TOPK];
__device__ int   g_cnt [NE];
__device__ int   g_off [NE+1];
__device__ int   g_fill[NE];
__device__ int   g_slot2tok[NSLOT];
__device__ int   g_slot_expert[NSLOT];
__device__ int   g_tok2slot[NTOK*TOPK];
__device__ float g_h[(size_t)NSLOT*FF];
__device__ float g_y[(size_t)NSLOT*DM];

// ---------------- helpers ----------------
__device__ __forceinline__ uint32_t f2tf(float x) {
    uint32_t r;
    asm("cvt.rna.tf32.f32 %0, %1;" : "=r"(r) : "f"(x));
    return r;
}

__device__ __forceinline__ void mma_tf32(float* c, const uint32_t* a, const uint32_t* b) {
    asm volatile("mma.sync.aligned.m16n8k8.row.col.f32.tf32.tf32.f32 "
                 "{%0,%1,%2,%3}, {%4,%5,%6,%7}, {%8,%9}, {%0,%1,%2,%3};"
                 : "+f"(c[0]), "+f"(c[1]), "+f"(c[2]), "+f"(c[3])
                 : "r"(a[0]), "r"(a[1]), "r"(a[2]), "r"(a[3]), "r"(b[0]), "r"(b[1]));
}

// ---------------- LayerNorm ----------------
__device__ __forceinline__ void ln_body(const float* __restrict__ x, const float* __restrict__ w,
                                        const float* __restrict__ b, float* __restrict__ out) {
    int t = blockIdx.x;
    const float* row = x + (size_t)t * DM;
    float s = 0.f, s2 = 0.f;
    for (int i = threadIdx.x; i < DM; i += blockDim.x) {
        float v = row[i]; s += v; s2 += v * v;
    }
    __shared__ float sh[64];
    for (int o = 16; o > 0; o >>= 1) {
        s  += __shfl_down_sync(0xffffffffu, s,  o);
        s2 += __shfl_down_sync(0xffffffffu, s2, o);
    }
    int wid = threadIdx.x >> 5, lane = threadIdx.x & 31;
    if (lane == 0) { sh[wid] = s; sh[wid + 32] = s2; }
    __syncthreads();
    if (threadIdx.x == 0) {
        float a = 0.f, c = 0.f;
        int nw = blockDim.x >> 5;
        for (int i = 0; i < nw; i++) { a += sh[i]; c += sh[i + 32]; }
        float mu  = a / DM;
        float var = c / DM - mu * mu;
        sh[0] = mu; sh[1] = rsqrtf(var + 1e-5f);
    }
    __syncthreads();
    float mu = sh[0], rs = sh[1];
    for (int i = threadIdx.x; i < DM; i += blockDim.x)
        out[(size_t)t * DM + i] = (row[i] - mu) * rs * w[i] + b[i];
}

__global__ void __launch_bounds__(256) ln1_kernel(const float* __restrict__ x,
                                                  const float* __restrict__ w,
                                                  const float* __restrict__ b) {
    ln_body(x, w, b, g_nx);
}
__global__ void __launch_bounds__(256) ln2_kernel(const float* __restrict__ w,
                                                  const float* __restrict__ b) {
    ln_body(g_x1, w, b, g_nx2);
}

// ============ tensor-core GEMM (tf32x3), 128x64 tile, 256 threads ============
// GROUPED: expert weights selected by g_slot_expert[m0]; early-out past g_off[NE]
// ROWMAP : A rows gathered via g_slot2tok (only with GROUPED)
// TRANSB : B given as [N,K] row-major (W^T applied), else [K,N] row-major
// ACT    : exact GELU on output
// RESID  : add resid[m*N+n]
template<bool GROUPED, bool ROWMAP, bool TRANSB, bool ACT, bool RESID>
__device__ __forceinline__ void mma_gemm_body(
    const float* __restrict__ A, int lda,
    const float* __restrict__ Wbase, size_t wstride,
    const float* __restrict__ biasbase, int bstride,
    const float* __restrict__ resid,
    float* __restrict__ C, int N, int K)
{
    __shared__ float As[BK][BM + 8];
    __shared__ float Bs[BK][BN + 8];

    int m0 = blockIdx.y * BM, n0 = blockIdx.x * BN;
    const float* Bm; const float* bias;
    if (GROUPED) {
        if (m0 >= g_off[NE]) return;
        int e = g_slot_expert[m0];
        Bm   = Wbase   + (size_t)e * wstride;
        bias = biasbase + (size_t)e * bstride;
    } else {
        Bm = Wbase; bias = biasbase;
    }

    int tid  = threadIdx.x;
    int lane = tid & 31, warp = tid >> 5;
    int wm = warp & 3, wn = warp >> 2;       // 4 x 2 warp grid, warp tile 32x32
    int g  = lane >> 2, tg = lane & 3;

    float c[2][4][4];
#pragma unroll
    for (int mt = 0; mt < 2; mt++)
#pragma unroll
        for (int nt = 0; nt < 4; nt++)
#pragma unroll
            for (int i = 0; i < 4; i++) c[mt][nt][i] = 0.f;

    // ---- staging index precompute ----
    // A: 128x16 = 512 float4; idx = s*256+tid; am=idx>>2, kq=idx&3
    int am[2], kqa[2], arow[2];
#pragma unroll
    for (int s = 0; s < 2; s++) {
        int idx = s * 256 + tid;
        am[s]  = idx >> 2;
        kqa[s] = idx & 3;
        int r = m0 + am[s];
        arow[s] = ROWMAP ? g_slot2tok[r] : r;
    }
    // B: NN: kb=tid>>4, nq=tid&15 ; NT: nb=tid>>2, kqb=tid&3
    int kb = tid >> 4, nq = tid & 15;
    int nb = tid >> 2, kqb = tid & 3;

    float4 ra[2], rb;

    // prologue load (k0 = 0)
#pragma unroll
    for (int s = 0; s < 2; s++) {
        if (!ROWMAP || arow[s] >= 0)
            ra[s] = *(const float4*)&A[(size_t)arow[s] * lda + kqa[s] * 4];
        else
            ra[s] = make_float4(0.f, 0.f, 0.f, 0.f);
    }
    if (TRANSB) rb = *(const float4*)&Bm[(size_t)(n0 + nb) * K + kqb * 4];
    else        rb = *(const float4*)&Bm[(size_t)kb * N + n0 + nq * 4];

    for (int k0 = 0; k0 < K; k0 += BK) {
        __syncthreads();
        // commit staged regs to smem
#pragma unroll
        for (int s = 0; s < 2; s++) {
            As[kqa[s] * 4 + 0][am[s]] = ra[s].x;
            As[kqa[s] * 4 + 1][am[s]] = ra[s].y;
            As[kqa[s] * 4 + 2][am[s]] = ra[s].z;
            As[kqa[s] * 4 + 3][am[s]] = ra[s].w;
        }
        if (TRANSB) {
            Bs[kqb * 4 + 0][nb] = rb.x;
            Bs[kqb * 4 + 1][nb] = rb.y;
            Bs[kqb * 4 + 2][nb] = rb.z;
            Bs[kqb * 4 + 3][nb] = rb.w;
        } else {
            *(float4*)&Bs[kb][nq * 4] = rb;
        }
        __syncthreads();

        // prefetch next K-slab
        int kn = k0 + BK;
        if (kn < K) {
#pragma unroll
            for (int s = 0; s < 2; s++) {
                if (!ROWMAP || arow[s] >= 0)
                    ra[s] = *(const float4*)&A[(size_t)arow[s] * lda + kn + kqa[s] * 4];
                else
                    ra[s] = make_float4(0.f, 0.f, 0.f, 0.f);
            }
            if (TRANSB) rb = *(const float4*)&Bm[(size_t)(n0 + nb) * K + kn + kqb * 4];
            else        rb = *(const float4*)&Bm[(size_t)(kn + kb) * N + n0 + nq * 4];
        }

        // compute: 2 k-steps of 8
#pragma unroll
        for (int ks = 0; ks < 2; ks++) {
            int k8 = ks * 8;
            uint32_t ahi[2][4], alo[2][4];
#pragma unroll
            for (int mt = 0; mt < 2; mt++) {
                int mb = wm * 32 + mt * 16;
                float a0 = As[k8 + tg][mb + g];
                float a1 = As[k8 + tg][mb + g + 8];
                float a2 = As[k8 + tg + 4][mb + g];
                float a3 = As[k8 + tg + 4][mb + g + 8];
                ahi[mt][0] = f2tf(a0); alo[mt][0] = f2tf(a0 - __uint_as_float(ahi[mt][0]));
                ahi[mt][1] = f2tf(a1); alo[mt][1] = f2tf(a1 - __uint_as_float(ahi[mt][1]));
                ahi[mt][2] = f2tf(a2); alo[mt][2] = f2tf(a2 - __uint_as_float(ahi[mt][2]));
                ahi[mt][3] = f2tf(a3); alo[mt][3] = f2tf(a3 - __uint_as_float(ahi[mt][3]));
            }
            uint32_t bhi[4][2], blo[4][2];
#pragma unroll
            for (int nt = 0; nt < 4; nt++) {
                int nbase = wn * 32 + nt * 8 + g;
                float b0 = Bs[k8 + tg][nbase];
                float b1 = Bs[k8 + tg + 4][nbase];
                bhi[nt][0] = f2tf(b0); blo[nt][0] = f2tf(b0 - __uint_as_float(bhi[nt][0]));
                bhi[nt][1] = f2tf(b1); blo[nt][1] = f2tf(b1 - __uint_as_float(bhi[nt][1]));
            }
#pragma unroll
            for (int mt = 0; mt < 2; mt++)
#pragma unroll
                for (int nt = 0; nt < 4; nt++) {
                    mma_tf32(c[mt][nt], alo[mt], bhi[nt]);
                    mma_tf32(c[mt][nt], ahi[mt], blo[nt]);
                    mma_tf32(c[mt][nt], ahi[mt], bhi[nt]);
                }
        }
    }

    // epilogue
#pragma unroll
    for (int mt = 0; mt < 2; mt++) {
        int r0 = m0 + wm * 32 + mt * 16 + g;
#pragma unroll
        for (int nt = 0; nt < 4; nt++) {
            int cc = n0 + wn * 32 + nt * 8 + tg * 2;
            float b0 = bias[cc], b1 = bias[cc + 1];
#pragma unroll
            for (int half = 0; half < 2; half++) {
                int r = r0 + half * 8;
                float v0 = c[mt][nt][half * 2 + 0] + b0;
                float v1 = c[mt][nt][half * 2 + 1] + b1;
                if (ACT) {
                    v0 = 0.5f * v0 * (1.0f + erff(v0 * 0.70710678118654752f));
                    v1 = 0.5f * v1 * (1.0f + erff(v1 * 0.70710678118654752f));
                }
                if (RESID) {
                    v0 += resid[(size_t)r * N + cc];
                    v1 += resid[(size_t)r * N + cc + 1];
                }
                C[(size_t)r * N + cc]     = v0;
                C[(size_t)r * N + cc + 1] = v1;
            }
        }
    }
}

__global__ void __launch_bounds__(256) gemm_qkv(const float* __restrict__ Wqkv,
                                                const float* __restrict__ bqkv) {
    mma_gemm_body<false, false, false, false, false>(g_nx, DM, Wqkv, 0, bqkv, 0, nullptr,
                                                     g_qkv, 3 * DM, DM);
}
__global__ void __launch_bounds__(256) gemm_wo(const float* __restrict__ Wo,
                                               const float* __restrict__ bo,
                                               const float* __restrict__ x) {
    mma_gemm_body<false, false, false, false, true>(g_attn, DM, Wo, 0, bo, 0, x,
                                                    g_x1, DM, DM);
}
__global__ void __launch_bounds__(256) moe_fc1(const float* __restrict__ fc1_w,
                                               const float* __restrict__ fc1_b) {
    mma_gemm_body<true, true, true, true, false>(g_nx2, DM, fc1_w, (size_t)FF * DM,
                                                 fc1_b, FF, nullptr, g_h, FF, DM);
}
__global__ void __launch_bounds__(256) moe_fc2(const float* __restrict__ fc2_w,
                                               const float* __restrict__ fc2_b) {
    mma_gemm_body<true, false, true, false, false>(g_h, FF, fc2_w, (size_t)DM * FF,
                                                   fc2_b, DM, nullptr, g_y, DM, FF);
}

// ============ tiled flash attention: 64 q-rows x 64 k-cols per block ============
__global__ void __launch_bounds__(256) attn_tile_kernel() {
    __shared__ float Qs[64][64];   // [d][q]  (Q transposed)
    __shared__ float KP[64][64];   // first K transposed [d][kk], then reused as P [kk][q]
    __shared__ float Vs[64][64];   // [kk][d]

    const float* __restrict__ qkv = g_qkv;
    int qt = blockIdx.x, h = blockIdx.y, b = blockIdx.z;
    int tid = threadIdx.x;
    int ty = tid >> 4, tx = tid & 15;

    // load Q tile transposed
#pragma unroll
    for (int r = 0; r < 4; r++) {
        int idx = r * 256 + tid;
        int q  = idx >> 4;
        int dq = idx & 15;
        float4 v = *(const float4*)&qkv[((size_t)(b * SEQL + qt * 64 + q)) * (3 * DM) + h * HD + dq * 4];
        Qs[dq * 4 + 0][q] = v.x;
        Qs[dq * 4 + 1][q] = v.y;
        Qs[dq * 4 + 2][q] = v.z;
        Qs[dq * 4 + 3][q] = v.w;
    }

    float o[4][4];
    float mrow[4], lrow[4];
#pragma unroll
    for (int i = 0; i < 4; i++) {
        mrow[i] = -1e30f; lrow[i] = 0.f;
#pragma unroll
        for (int j = 0; j < 4; j++) o[i][j] = 0.f;
    }

    for (int kt = 0; kt <= qt; kt++) {
        __syncthreads();   // prior tile's PV reads of KP/Vs done
        // load K transposed + V natural
#pragma unroll
        for (int r = 0; r < 4; r++) {
            int idx = r * 256 + tid;
            int kk = idx >> 4;
            int dq = idx & 15;
            size_t base = ((size_t)(b * SEQL + kt * 64 + kk)) * (3 * DM) + h * HD + dq * 4;
            float4 kv = *(const float4*)&qkv[base + DM];
            KP[dq * 4 + 0][kk] = kv.x;
            KP[dq * 4 + 1][kk] = kv.y;
            KP[dq * 4 + 2][kk] = kv.z;
            KP[dq * 4 + 3][kk] = kv.w;
            *(float4*)&Vs[kk][dq * 4] = *(const float4*)&qkv[base + 2 * DM];
        }
        __syncthreads();

        // S = Q K^T  (rows q = ty*4+i, cols kk = tx*4+j)
        float s[4][4] = {};
#pragma unroll 8
        for (int d = 0; d < 64; d++) {
            float4 aq = *(const float4*)&Qs[d][ty * 4];
            float4 bk = *(const float4*)&KP[d][tx * 4];
            float a_[4] = {aq.x, aq.y, aq.z, aq.w};
            float b_[4] = {bk.x, bk.y, bk.z, bk.w};
#pragma unroll
            for (int i = 0; i < 4; i++)
#pragma unroll
                for (int j = 0; j < 4; j++) s[i][j] += a_[i] * b_[j];
        }

        // scale + causal mask + online softmax update
        bool diag = (kt == qt);
#pragma unroll
        for (int i = 0; i < 4; i++) {
            int qloc = ty * 4 + i;
            float tm = -1e30f;
#pragma unroll
            for (int j = 0; j < 4; j++) {
                float sv = s[i][j] * 0.125f;
                if (diag && (tx * 4 + j) > qloc) sv = -1e30f;
                s[i][j] = sv;
                tm = fmaxf(tm, sv);
            }
            tm = fmaxf(tm, __shfl_xor_sync(0xffffffffu, tm, 1));
            tm = fmaxf(tm, __shfl_xor_sync(0xffffffffu, tm, 2));
            tm = fmaxf(tm, __shfl_xor_sync(0xffffffffu, tm, 4));
            tm = fmaxf(tm, __shfl_xor_sync(0xffffffffu, tm, 8));
            float nm = fmaxf(mrow[i], tm);
            float rs = 0.f;
#pragma unroll
            for (int j = 0; j < 4; j++) {
                float p = __expf(s[i][j] - nm);
                s[i][j] = p;
                rs += p;
            }
            rs += __shfl_xor_sync(0xffffffffu, rs, 1);
            rs += __shfl_xor_sync(0xffffffffu, rs, 2);
            rs += __shfl_xor_sync(0xffffffffu, rs, 4);
            rs += __shfl_xor_sync(0xffffffffu, rs, 8);
            float sc2 = __expf(mrow[i] - nm);
            mrow[i] = nm;
            lrow[i] = lrow[i] * sc2 + rs;
#pragma unroll
            for (int j = 0; j < 4; j++) o[i][j] *= sc2;
        }

        __syncthreads();   // all warps done reading KP as K
        // store P into KP as [kk][q]
#pragma unroll
        for (int j = 0; j < 4; j++)
            *(float4*)&KP[tx * 4 + j][ty * 4] = make_float4(s[0][j], s[1][j], s[2][j], s[3][j]);
        __syncthreads();

        // O += P V  (rows q = ty*4+i, cols d = tx*4+j)
#pragma unroll 8
        for (int kk = 0; kk < 64; kk++) {
            float4 ap = *(const float4*)&KP[kk][ty * 4];
            float4 bv = *(const float4*)&Vs[kk][tx * 4];
            float a_[4] = {ap.x, ap.y, ap.z, ap.w};
            float b_[4] = {bv.x, bv.y, bv.z, bv.w};
#pragma unroll
            for (int i = 0; i < 4; i++)
#pragma unroll
                for (int j = 0; j < 4; j++) o[i][j] += a_[i] * b_[j];
        }
    }

    // write out
#pragma unroll
    for (int i = 0; i < 4; i++) {
        float inv = 1.f / lrow[i];
        float4 ov = make_float4(o[i][0] * inv, o[i][1] * inv, o[i][2] * inv, o[i][3] * inv);
        *(float4*)&g_attn[((size_t)(b * SEQL + qt * 64 + ty * 4 + i)) * DM + h * HD + tx * 4] = ov;
    }
}

// ---------------- gating: top-2 + softmax over selected logits ----------------
__global__ void __launch_bounds__(256) gate_kernel(const float* __restrict__ gW) {
    int t = blockIdx.x, tid = threadIdx.x;        // 256 threads = 8 warps = 8 experts
    int e = tid >> 5, lane = tid & 31;
    float s = 0.f;
    for (int d = lane; d < DM; d += 32) s += g_nx2[(size_t)t * DM + d] * gW[(size_t)d * NE + e];
    for (int o = 16; o > 0; o >>= 1) s += __shfl_down_sync(0xffffffffu, s, o);
    __shared__ float lg[NE];
    if (lane == 0) lg[e] = s;
    __syncthreads();
    if (tid == 0) {
        int i0 = 0; float v0 = lg[0];
        for (int i = 1; i < NE; i++) if (lg[i] > v0) { v0 = lg[i]; i0 = i; }
        int i1 = -1; float v1 = -1e30f;
        for (int i = 0; i < NE; i++) { if (i == i0) continue; if (lg[i] > v1) { v1 = lg[i]; i1 = i; } }
        float e1 = expf(v1 - v0), sum = 1.f + e1;
        g_top_idx[t * 2] = i0; g_top_idx[t * 2 + 1] = i1;
        g_top_w[t * 2] = 1.f / sum; g_top_w[t * 2 + 1] = e1 / sum;
    }
}

// ---------------- routing (expert offsets 128-aligned) ----------------
__global__ void route_zero() {
    int i = blockIdx.x * blockDim.x + threadIdx.x;
    if (i < NE) { g_cnt[i] = 0; g_fill[i] = 0; }
    if (i < NSLOT) g_slot2tok[i] = -1;
}
__global__ void route_count() {
    int i = blockIdx.x * blockDim.x + threadIdx.x;
    if (i < NTOK * TOPK) atomicAdd(&g_cnt[g_top_idx[i]], 1);
}
__global__ void route_scan() {
    g_off[0] = 0;
    for (int e = 0; e < NE; e++)
        g_off[e + 1] = g_off[e] + ((g_cnt[e] + BM - 1) / BM) * BM;   // 128-aligned per expert
}
__global__ void route_fill_expert() {
    int s = blockIdx.x * blockDim.x + threadIdx.x;
    if (s >= NSLOT) return;
    int e = NE - 1;
    for (int i = 0; i < NE; i++) if (s >= g_off[i] && s < g_off[i + 1]) { e = i; break; }
    g_slot_expert[s] = e;
}
__global__ void route_assign() {
    int i = blockIdx.x * blockDim.x + threadIdx.x;
    if (i >= NTOK * TOPK) return;
    int e = g_top_idx[i];
    int pos = atomicAdd(&g_fill[e], 1);
    int slot = g_off[e] + pos;
    g_slot2tok[slot] = i >> 1;
    g_tok2slot[i] = slot;
}

// ---------------- final combine: out = x1 + sum_k w_k * y[slot_k] ----------------
__global__ void __launch_bounds__(256) combine_kernel(float* __restrict__ out) {
    int t = blockIdx.x;
    int s0 = g_tok2slot[t * 2], s1 = g_tok2slot[t * 2 + 1];
    float w0 = g_top_w[t * 2], w1 = g_top_w[t * 2 + 1];
    for (int i = threadIdx.x; i < DM; i += blockDim.x)
        out[(size_t)t * DM + i] =
            g_x1[(size_t)t * DM + i] + w0 * g_y[(size_t)s0 * DM + i] + w1 * g_y[(size_t)s1 * DM + i];
}

// ---------------- launch: kernel launches ONLY ----------------
extern "C" void kernel_launch(void* const* d_in, const int* in_sizes, int n_in,
                              void* d_out, int out_size) {
    const float* x     = (const float*)d_in[0];
    const float* ln1_w = (const float*)d_in[1];
    const float* ln1_b = (const float*)d_in[2];
    const float* ln2_w = (const float*)d_in[3];
    const float* ln2_b = (const float*)d_in[4];
    const float* Wqkv  = (const float*)d_in[5];
    const float* bqkv  = (const float*)d_in[6];
    const float* Wo    = (const float*)d_in[7];
    const float* bo    = (const float*)d_in[8];
    const float* gateW = (const float*)d_in[9];
    const float* fc1_w = (const float*)d_in[10];
    const float* fc1_b = (const float*)d_in[11];
    const float* fc2_w = (const float*)d_in[12];
    const float* fc2_b = (const float*)d_in[13];
    float* out = (float*)d_out;

    // 1) LN1: g_nx = LN(x)
    ln1_kernel<<<NTOK, 256>>>(x, ln1_w, ln1_b);
    // 2) QKV projection: g_qkv = g_nx @ Wqkv + bqkv
    gemm_qkv<<<dim3(3 * DM / BN, NTOK / BM), 256>>>(Wqkv, bqkv);
    // 3) tiled causal flash attention -> g_attn
    attn_tile_kernel<<<dim3(SEQL / 64, NH, BATCH), 256>>>();
    // 4) output projection + residual: g_x1 = x + g_attn @ Wo + bo
    gemm_wo<<<dim3(DM / BN, NTOK / BM), 256>>>(Wo, bo, x);
    // 5) LN2: g_nx2 = LN(g_x1)
    ln2_kernel<<<NTOK, 256>>>(ln2_w, ln2_b);
    // 6) gate top-2
    gate_kernel<<<NTOK, 256>>>(gateW);
    // 7) routing
    route_zero<<<(NSLOT + 255) / 256, 256>>>();
    route_count<<<(NTOK * TOPK + 255) / 256, 256>>>();
    route_scan<<<1, 1>>>();
    route_fill_expert<<<(NSLOT + 255) / 256, 256>>>();
    route_assign<<<(NTOK * TOPK + 255) / 256, 256>>>();
    // 8) fc1: g_h = gelu(gather(g_nx2) @ fc1_w[e]^T + fc1_b[e])
    moe_fc1<<<dim3(FF / BN, NSLOT / BM), 256>>>(fc1_w, fc1_b);
    // 9) fc2: g_y = g_h @ fc2_w[e]^T + fc2_b[e]
    moe_fc2<<<dim3(DM / BN, NSLOT / BM), 256>>>(fc2_w, fc2_b);
    // 10) combine: out = g_x1 + w0*y0 + w1*y1
    combine_kernel<<<NTOK, 256>>>(out);
    (void)in_sizes; (void)n_in; (void)out_size;
}